// round 10
// baseline (speedup 1.0000x reference)
#include <cuda_runtime.h>
#include <math.h>

// Problem constants
#define BB      1024
#define T_TOT   576
#define T_INP   512
#define T_TASK  64
#define HH      100
#define GG      400
#define DF      9
#define BS      8        // batch rows per block (4 row-pairs for f32x2)
#define NTHREADS 512
#define NBLOCKS  128     // 128 * 8 = 1024 exactly

#define KHALF   50       // k per half (2-way k split)
#define KPADH   52       // padded half (multiple of 4)
#define KHT     104      // hT k-extent (2 halves)
#define WROW    112      // whT floats per column (2 x 56)
#define WHALF   56

struct __align__(16) Smem {
    float whT[GG * WROW];       // W_h^T, per-column rows, split in k-halves   179200 B
    float hT[KHT * 8];          // h pair-interleaved: hT[kh*8 + row]            3328 B
    float hrow[8 * 104];        // h row-major (for logits)                      3328 B
    float z4[2 * 4 * 200 * 4];  // packed partials [ks][pair][colPair][4]       25600 B
    float sT[DF * 8];           // s pair-interleaved: sT[f*8 + row]              288 B
    float woutT[DF * 104];      // W_out^T, d-major padded                       3744 B
    float win[81];
    float wtask[81];
    float bin[DF];
    float btask[DF];
    float bout[DF];
    float raw[72];              // prefetched raw features (8 rows x 9)
    float lg[72];               // logits
};
// ~216.7 KB dynamic smem -> 1 block/SM

__device__ __forceinline__ float sigmoidf_(float x) {
    return __fdividef(1.0f, 1.0f + __expf(-x));
}
__device__ __forceinline__ float tanhf_(float x) {
    return 1.0f - __fdividef(2.0f, 1.0f + __expf(2.0f * x));
}

// packed fp32x2 helpers
__device__ __forceinline__ void fma2(unsigned long long& acc, unsigned long long ab,
                                     unsigned long long cd) {
    asm("fma.rn.f32x2 %0, %1, %2, %0;" : "+l"(acc) : "l"(ab), "l"(cd));
}
__device__ __forceinline__ unsigned long long dup2(float w) {
    unsigned long long r;
    asm("mov.b64 %0, {%1, %1};" : "=l"(r) : "f"(w));
    return r;
}

__global__ void __launch_bounds__(NTHREADS, 1)
lstm_fused_kernel(const float* __restrict__ input,  // [1024,512,9]
                  const float* __restrict__ task,   // [1024,64,9]
                  const float* __restrict__ W_in,   // [9,9]
                  const float* __restrict__ b_in,   // [9]
                  const float* __restrict__ W_task, // [9,9]
                  const float* __restrict__ b_task, // [9]
                  const float* __restrict__ W_x,    // [9,400]
                  const float* __restrict__ W_h,    // [100,400]
                  const float* __restrict__ b_lstm, // [400]
                  const float* __restrict__ W_out,  // [100,9]
                  const float* __restrict__ b_out,  // [9]
                  float* __restrict__ out)          // [1024,576,9]
{
    extern __shared__ unsigned char smem_raw[];
    Smem* sm = reinterpret_cast<Smem*>(smem_raw);

    const int tid  = threadIdx.x;
    const int row0 = blockIdx.x * BS;

    // ---------------- prologue ----------------
    // whT[col*112 + ks*56 + kloc] = W_h[(ks*50+kloc)*400 + col]  (kloc<50), else 0
    for (int idx = tid; idx < GG * WROW; idx += NTHREADS) {
        int col  = idx / WROW;
        int rem  = idx - col * WROW;
        int ks   = rem / WHALF;
        int kloc = rem - ks * WHALF;
        sm->whT[idx] = (kloc < KHALF) ? W_h[(ks * KHALF + kloc) * GG + col] : 0.0f;
    }
    for (int idx = tid; idx < DF * 104; idx += NTHREADS) {
        int d = idx / 104, k = idx - d * 104;
        sm->woutT[idx] = (k < HH) ? W_out[k * DF + d] : 0.0f;
    }
    if (tid < 81) { sm->win[tid] = W_in[tid]; sm->wtask[tid] = W_task[tid]; }
    if (tid < DF) { sm->bin[tid] = b_in[tid]; sm->btask[tid] = b_task[tid]; sm->bout[tid] = b_out[tid]; }
    for (int idx = tid; idx < KHT * 8; idx += NTHREADS) sm->hT[idx] = 0.0f;

    // ph1 thread mapping: 400 threads = 200 column-pairs x 2 k-halves
    const int  pid = (tid < GG) ? (tid % 200) : 0;
    const int  ks  = (tid < GG) ? (tid / 200) : 0;
    const int  cA  = 2 * pid, cB = 2 * pid + 1;
    float wxA[9], wxB[9];
    float blA = 0.0f, blB = 0.0f;
    if (tid < 200) {   // only ks==0 threads carry bias + s-part
#pragma unroll
        for (int f = 0; f < 9; f++) {
            wxA[f] = W_x[f * GG + cA];
            wxB[f] = W_x[f * GG + cB];
        }
        blA = b_lstm[cA];
        blB = b_lstm[cB];
    } else {
#pragma unroll
        for (int f = 0; f < 9; f++) { wxA[f] = 0.0f; wxB[f] = 0.0f; }
    }

    // ph2 gate mapping: thread g<400 owns rows (2p, 2p+1) at unit u
    const int  gu = tid % HH;
    const int  gp = (tid < GG) ? (tid / HH) : 0;
    const int  kh = gu + (gu >= KHALF ? 2 : 0);
    float c0 = 0.0f, c1 = 0.0f;

    // prefetch mapping
    const int pf = tid - 432;   // [0,72) for prefetch threads

    __syncthreads();

    // raw(t=0) then sT(0)
    if (tid < 72) sm->raw[tid] = input[(row0 + tid / 9) * (size_t)(T_INP * 9) + (tid % 9)];
    __syncthreads();
    if (tid < 72) {
        int sr = tid / 9, sf = tid - sr * 9;
        float a = sm->bin[sf];
#pragma unroll
        for (int f = 0; f < 9; f++) a += sm->raw[sr * 9 + f] * sm->win[f * 9 + sf];
        sm->sT[sf * 8 + sr] = fmaxf(a, 0.0f);
    }
    __syncthreads();

    // ---------------- the 576-step scan ----------------
    for (int t = 0; t < T_TOT; t++) {
        // ---- prefetch issue (idle-in-ph1 threads): latency hidden under ph1
        float pv = 0.0f;
        if (pf >= 0 && pf < 72 && (t + 1) < T_TOT) {
            int tn = t + 1;
            int pr = pf / 9, pc = pf - pr * 9;
            pv = (tn < T_INP)
                     ? input[((size_t)(row0 + pr) * T_INP + tn) * 9 + pc]
                     : task[((size_t)(row0 + pr) * T_TASK + (tn - T_INP)) * 9 + pc];
        }

        // ---- ph1: z partials, 2 columns x 4 row-pairs per thread, f32x2 FMA
        if (tid < GG) {
            unsigned long long aA0, aA1, aA2, aA3, aB0, aB1, aB2, aB3;
            if (ks == 0) {
                unsigned long long ba = dup2(blA), bb = dup2(blB);
                aA0 = ba; aA1 = ba; aA2 = ba; aA3 = ba;
                aB0 = bb; aB1 = bb; aB2 = bb; aB3 = bb;
#pragma unroll
                for (int f = 0; f < 9; f++) {
                    unsigned long long wa = dup2(wxA[f]);
                    unsigned long long wb = dup2(wxB[f]);
                    ulonglong2 s01 = *reinterpret_cast<const ulonglong2*>(&sm->sT[f * 8]);
                    ulonglong2 s23 = *reinterpret_cast<const ulonglong2*>(&sm->sT[f * 8 + 4]);
                    fma2(aA0, wa, s01.x); fma2(aA1, wa, s01.y);
                    fma2(aA2, wa, s23.x); fma2(aA3, wa, s23.y);
                    fma2(aB0, wb, s01.x); fma2(aB1, wb, s01.y);
                    fma2(aB2, wb, s23.x); fma2(aB3, wb, s23.y);
                }
            } else {
                aA0 = aA1 = aA2 = aA3 = 0ull;
                aB0 = aB1 = aB2 = aB3 = 0ull;
            }

            const float4* wa4p = reinterpret_cast<const float4*>(&sm->whT[cA * WROW + ks * WHALF]);
            const float4* wb4p = reinterpret_cast<const float4*>(&sm->whT[cB * WROW + ks * WHALF]);
            const float*  hbase = &sm->hT[(ks * KPADH) * 8];

#define STEPQ(WA, WB, HIDX)                                                            \
            {                                                                          \
                ulonglong2 hlo = *reinterpret_cast<const ulonglong2*>(&hbase[(HIDX)]); \
                ulonglong2 hhi = *reinterpret_cast<const ulonglong2*>(&hbase[(HIDX) + 4]); \
                unsigned long long da = dup2(WA);                                      \
                unsigned long long db = dup2(WB);                                      \
                fma2(aA0, da, hlo.x); fma2(aA1, da, hlo.y);                            \
                fma2(aA2, da, hhi.x); fma2(aA3, da, hhi.y);                            \
                fma2(aB0, db, hlo.x); fma2(aB1, db, hlo.y);                            \
                fma2(aB2, db, hhi.x); fma2(aB3, db, hhi.y);                            \
            }

#pragma unroll
            for (int kk = 0; kk < 13; kk++) {
                float4 wa4 = wa4p[kk];
                float4 wb4 = wb4p[kk];
                int hb = kk * 32;
                STEPQ(wa4.x, wb4.x, hb + 0)
                STEPQ(wa4.y, wb4.y, hb + 8)
                STEPQ(wa4.z, wb4.z, hb + 16)
                STEPQ(wa4.w, wb4.w, hb + 24)
            }
#undef STEPQ

            // packed store: one STS.128 per row-pair
            float* zb = &sm->z4[ks * 3200 + pid * 4];
            ulonglong2 v;
            v.x = aA0; v.y = aB0; *reinterpret_cast<ulonglong2*>(zb)        = v;
            v.x = aA1; v.y = aB1; *reinterpret_cast<ulonglong2*>(zb + 800)  = v;
            v.x = aA2; v.y = aB2; *reinterpret_cast<ulonglong2*>(zb + 1600) = v;
            v.x = aA3; v.y = aB3; *reinterpret_cast<ulonglong2*>(zb + 2400) = v;
        }
        __syncthreads();

        // ---- ph2: gates (2 units = one row-pair per thread); prefetch lands in raw
        if (tid < GG) {
            float2 zc[4];
#pragma unroll
            for (int c = 0; c < 4; c++) {
                int j  = gu + c * HH;
                int bi = (gp * 200 + (j >> 1)) * 4 + ((j & 1) << 1);
                float2 a = *reinterpret_cast<const float2*>(&sm->z4[bi]);
                float2 b = *reinterpret_cast<const float2*>(&sm->z4[3200 + bi]);
                zc[c] = make_float2(a.x + b.x, a.y + b.y);
            }
            float gi0 = sigmoidf_(zc[0].x), gf0 = sigmoidf_(zc[1].x);
            float gg0 = tanhf_(zc[2].x),    go0 = sigmoidf_(zc[3].x);
            c0 = gf0 * c0 + gi0 * gg0;
            float h0 = go0 * tanhf_(c0);

            float gi1 = sigmoidf_(zc[0].y), gf1 = sigmoidf_(zc[1].y);
            float gg1 = tanhf_(zc[2].y),    go1 = sigmoidf_(zc[3].y);
            c1 = gf1 * c1 + gi1 * gg1;
            float h1 = go1 * tanhf_(c1);

            *reinterpret_cast<float2*>(&sm->hT[kh * 8 + 2 * gp]) = make_float2(h0, h1);
            sm->hrow[(2 * gp) * 104 + gu]     = h0;
            sm->hrow[(2 * gp + 1) * 104 + gu] = h1;
        }
        if (pf >= 0 && pf < 72 && (t + 1) < T_TOT) sm->raw[pf] = pv;
        __syncthreads();

        // ---- ph3a: logits (tid 0..71)  ||  encode s(t+1) (tid 72..143)
        if (tid < 72) {
            int lr = tid / 9, ld = tid - lr * 9;
            const float4* hr = reinterpret_cast<const float4*>(&sm->hrow[lr * 104]);
            const float4* wd = reinterpret_cast<const float4*>(&sm->woutT[ld * 104]);
            float a0 = 0.f, a1 = 0.f, a2 = 0.f, a3 = 0.f;
#pragma unroll
            for (int kk = 0; kk < 25; kk++) {
                float4 h4 = hr[kk];
                float4 w4 = wd[kk];
                a0 += h4.x * w4.x;
                a1 += h4.y * w4.y;
                a2 += h4.z * w4.z;
                a3 += h4.w * w4.w;
            }
            sm->lg[tid] = sm->bout[ld] + (a0 + a1) + (a2 + a3);
        } else if (tid < 144 && (t + 1) < T_TOT) {
            int sn = tid - 72;
            int sr = sn / 9, sf = sn - sr * 9;
            const float* We = ((t + 1) < T_INP) ? sm->win : sm->wtask;
            const float* be = ((t + 1) < T_INP) ? sm->bin : sm->btask;
            float a = be[sf];
#pragma unroll
            for (int f = 0; f < 9; f++) a += sm->raw[sr * 9 + f] * We[f * 9 + sf];
            sm->sT[sf * 8 + sr] = fmaxf(a, 0.0f);
        }
        __syncthreads();

        // ---- ph3b: softmax + store (one thread per batch row; ordering vs next
        //      ph3a's lg write is guaranteed by the ph1+ph2 barriers in between)
        if (tid < BS) {
            float l[9];
            float m = -1e30f;
#pragma unroll
            for (int d = 0; d < 9; d++) { l[d] = sm->lg[tid * 9 + d]; m = fmaxf(m, l[d]); }
            float ssum = 0.0f;
#pragma unroll
            for (int d = 0; d < 9; d++) { l[d] = __expf(l[d] - m); ssum += l[d]; }
            float inv = __fdividef(1.0f, ssum);
            float* op = out + ((size_t)(row0 + tid) * T_TOT + t) * 9;
#pragma unroll
            for (int d = 0; d < 9; d++) op[d] = l[d] * inv;
        }
    }
}

extern "C" void kernel_launch(void* const* d_in, const int* in_sizes, int n_in,
                              void* d_out, int out_size) {
    const float* input  = (const float*)d_in[0];
    const float* task   = (const float*)d_in[1];
    const float* W_in   = (const float*)d_in[2];
    const float* b_in   = (const float*)d_in[3];
    const float* W_task = (const float*)d_in[4];
    const float* b_task = (const float*)d_in[5];
    const float* W_x    = (const float*)d_in[6];
    const float* W_h    = (const float*)d_in[7];
    const float* b_lstm = (const float*)d_in[8];
    const float* W_out  = (const float*)d_in[9];
    const float* b_out  = (const float*)d_in[10];
    float* out = (float*)d_out;

    cudaFuncSetAttribute(lstm_fused_kernel,
                         cudaFuncAttributeMaxDynamicSharedMemorySize,
                         (int)sizeof(Smem));
    lstm_fused_kernel<<<NBLOCKS, NTHREADS, sizeof(Smem)>>>(
        input, task, W_in, b_in, W_task, b_task,
        W_x, W_h, b_lstm, W_out, b_out, out);
}

// round 11
// speedup vs baseline: 2.1317x; 2.1317x over previous
#include <cuda_runtime.h>
#include <math.h>

// Problem constants
#define BB      1024
#define T_TOT   576
#define T_INP   512
#define T_TASK  64
#define HH      100
#define GG      400
#define DF      9
#define BS      8        // batch rows per block (4 row-pairs for f32x2)
#define NTHREADS 512
#define NBLOCKS  128     // 128 * 8 = 1024 exactly

#define KHALF   50       // k per half (2-way k split)
#define KPADH   52       // padded half (multiple of 4)
#define KHT     104      // hT k-extent (2 halves of 52)
#define PROW    108      // whT floats per (pair,ks) slot: 27 x 16B units (odd -> conflict-free)

struct __align__(16) Smem {
    float whT[400 * PROW];      // pair-interleaved W_h^T                      172800 B
    float hT[KHT * 8];          // h pair-interleaved: hT[kh*8 + row]            3328 B
    float hrow[8 * 104];        // h row-major (for logits)                      3328 B
    float z4[2 * 4 * 200 * 4];  // packed partials [ks][rowpair][colpair][4]    25600 B
    float sT[DF * 8];           // s pair-interleaved: sT[f*8 + row]              288 B
    float woutT[DF * 104];      // W_out^T, d-major padded                       3744 B
    float win[81];
    float wtask[81];
    float bin[DF];
    float btask[DF];
    float bout[DF];
    float rawS[2][72];          // double-buffered raw features (distance-2 prefetch)
    float lg[72];               // logits
};
// ~210.7 KB dynamic smem -> 1 block/SM

__device__ __forceinline__ float sigmoidf_(float x) {
    return __fdividef(1.0f, 1.0f + __expf(-x));
}
__device__ __forceinline__ float tanhf_(float x) {
    return 1.0f - __fdividef(2.0f, 1.0f + __expf(2.0f * x));
}

__device__ __forceinline__ void fma2(unsigned long long& acc, unsigned long long ab,
                                     unsigned long long cd) {
    asm("fma.rn.f32x2 %0, %1, %2, %0;" : "+l"(acc) : "l"(ab), "l"(cd));
}
__device__ __forceinline__ unsigned long long dup2(float w) {
    unsigned long long r;
    asm("mov.b64 %0, {%1, %1};" : "=l"(r) : "f"(w));
    return r;
}

__global__ void __launch_bounds__(NTHREADS, 1)
lstm_fused_kernel(const float* __restrict__ input,  // [1024,512,9]
                  const float* __restrict__ task,   // [1024,64,9]
                  const float* __restrict__ W_in,   // [9,9]
                  const float* __restrict__ b_in,   // [9]
                  const float* __restrict__ W_task, // [9,9]
                  const float* __restrict__ b_task, // [9]
                  const float* __restrict__ W_x,    // [9,400]
                  const float* __restrict__ W_h,    // [100,400]
                  const float* __restrict__ b_lstm, // [400]
                  const float* __restrict__ W_out,  // [100,9]
                  const float* __restrict__ b_out,  // [9]
                  float* __restrict__ out)          // [1024,576,9]
{
    extern __shared__ unsigned char smem_raw[];
    Smem* sm = reinterpret_cast<Smem*>(smem_raw);

    const int tid  = threadIdx.x;
    const int row0 = blockIdx.x * BS;

    // ---------------- prologue ----------------
    // whT[(ks*200+pid)*108 + kk*8 + l8], l8<4 -> col 2*pid, l8>=4 -> col 2*pid+1,
    // kloc = kk*4 + (l8&3), k = ks*50+kloc; zero-pad kloc>=50 and rem>=104.
    for (int idx = tid; idx < 400 * PROW; idx += NTHREADS) {
        int slot = idx / PROW;
        int rem  = idx - slot * PROW;
        float v = 0.0f;
        if (rem < 104) {
            int ks   = slot / 200;
            int pid  = slot - ks * 200;
            int kk   = rem >> 3;
            int l8   = rem & 7;
            int col  = 2 * pid + (l8 >> 2);
            int kloc = kk * 4 + (l8 & 3);
            if (kloc < KHALF) v = W_h[(ks * KHALF + kloc) * GG + col];
        }
        sm->whT[idx] = v;
    }
    for (int idx = tid; idx < DF * 104; idx += NTHREADS) {
        int d = idx / 104, k = idx - d * 104;
        sm->woutT[idx] = (k < HH) ? W_out[k * DF + d] : 0.0f;
    }
    if (tid < 81) { sm->win[tid] = W_in[tid]; sm->wtask[tid] = W_task[tid]; }
    if (tid < DF) { sm->bin[tid] = b_in[tid]; sm->btask[tid] = b_task[tid]; sm->bout[tid] = b_out[tid]; }
    for (int idx = tid; idx < KHT * 8; idx += NTHREADS) sm->hT[idx] = 0.0f;

    // ph1 GEMM mapping
    const int  pid = (tid < GG) ? (tid % 200) : 0;
    const int  ks  = (tid < GG) ? (tid / 200) : 0;
    float wxA[9], wxB[9];
    float blA = 0.0f, blB = 0.0f;
    if (tid < 200) {
#pragma unroll
        for (int f = 0; f < 9; f++) {
            wxA[f] = W_x[f * GG + 2 * tid];
            wxB[f] = W_x[f * GG + 2 * tid + 1];
        }
        blA = b_lstm[2 * tid];
        blB = b_lstm[2 * tid + 1];
    } else {
#pragma unroll
        for (int f = 0; f < 9; f++) { wxA[f] = 0.0f; wxB[f] = 0.0f; }
    }

    // ph2 gate mapping: thread owns rows (2gp, 2gp+1) at unit gu
    const int  gu = tid % HH;
    const int  gp = (tid < GG) ? (tid / HH) : 0;
    const int  kh = gu + (gu >= KHALF ? 2 : 0);
    float c0 = 0.0f, c1 = 0.0f;

    __syncthreads();

    // prime: raw(0) -> rawS[0], raw(1) -> rawS[1], then s(0)
    if (tid < 72) {
        sm->rawS[0][tid] = input[(size_t)(row0 + tid / 9) * (T_INP * 9) + (tid % 9)];
    } else if (tid < 144) {
        int j = tid - 72;
        sm->rawS[1][j] = input[((size_t)(row0 + j / 9) * T_INP + 1) * 9 + (j % 9)];
    }
    __syncthreads();
    if (tid < 72) {
        int sr = tid / 9, sf = tid - sr * 9;
        float a = sm->bin[sf];
#pragma unroll
        for (int f = 0; f < 9; f++) a += sm->rawS[0][sr * 9 + f] * sm->win[f * 9 + sf];
        sm->sT[sf * 8 + sr] = fmaxf(a, 0.0f);
    }
    __syncthreads();

    // ---------------- the 576-step scan ----------------
    for (int t = 0; t < T_TOT; t++) {
        // ---- ph1: GEMM [0..399] || logits(t-1) [416..447] || prefetch raw(t+2) [448..511]
        float pv0 = 0.0f, pv1 = 0.0f;
        if (tid >= 448 && (t + 2) < T_TOT) {
            int tn = t + 2;
            int j  = tid - 448;
            {
                int pr = j / 9, pc = j - pr * 9;
                pv0 = (tn < T_INP)
                          ? input[((size_t)(row0 + pr) * T_INP + tn) * 9 + pc]
                          : task[((size_t)(row0 + pr) * T_TASK + (tn - T_INP)) * 9 + pc];
            }
            if (j < 8) {
                int j2 = j + 64;
                int pr = j2 / 9, pc = j2 - pr * 9;
                pv1 = (tn < T_INP)
                          ? input[((size_t)(row0 + pr) * T_INP + tn) * 9 + pc]
                          : task[((size_t)(row0 + pr) * T_TASK + (tn - T_INP)) * 9 + pc];
            }
        }

        if (tid < GG) {
            unsigned long long aA0, aA1, aA2, aA3, aB0, aB1, aB2, aB3;
            if (ks == 0) {
                unsigned long long ba = dup2(blA), bb = dup2(blB);
                aA0 = ba; aA1 = ba; aA2 = ba; aA3 = ba;
                aB0 = bb; aB1 = bb; aB2 = bb; aB3 = bb;
#pragma unroll
                for (int f = 0; f < 9; f++) {
                    unsigned long long wa = dup2(wxA[f]);
                    unsigned long long wb = dup2(wxB[f]);
                    ulonglong2 s01 = *reinterpret_cast<const ulonglong2*>(&sm->sT[f * 8]);
                    ulonglong2 s23 = *reinterpret_cast<const ulonglong2*>(&sm->sT[f * 8 + 4]);
                    fma2(aA0, wa, s01.x); fma2(aA1, wa, s01.y);
                    fma2(aA2, wa, s23.x); fma2(aA3, wa, s23.y);
                    fma2(aB0, wb, s01.x); fma2(aB1, wb, s01.y);
                    fma2(aB2, wb, s23.x); fma2(aB3, wb, s23.y);
                }
            } else {
                aA0 = aA1 = aA2 = aA3 = 0ull;
                aB0 = aB1 = aB2 = aB3 = 0ull;
            }

            const float*  wbase = &sm->whT[(ks * 200 + pid) * PROW];
            const float*  hbase = &sm->hT[(ks * KPADH) * 8];

#define STEPQ(WA, WB, HIDX)                                                            \
            {                                                                          \
                ulonglong2 hlo = *reinterpret_cast<const ulonglong2*>(&hbase[(HIDX)]); \
                ulonglong2 hhi = *reinterpret_cast<const ulonglong2*>(&hbase[(HIDX) + 4]); \
                unsigned long long da = dup2(WA);                                      \
                unsigned long long db = dup2(WB);                                      \
                fma2(aA0, da, hlo.x); fma2(aA1, da, hlo.y);                            \
                fma2(aA2, da, hhi.x); fma2(aA3, da, hhi.y);                            \
                fma2(aB0, db, hlo.x); fma2(aB1, db, hlo.y);                            \
                fma2(aB2, db, hhi.x); fma2(aB3, db, hhi.y);                            \
            }

#pragma unroll
            for (int kk = 0; kk < 13; kk++) {
                float4 wa4 = *reinterpret_cast<const float4*>(wbase + kk * 8);
                float4 wb4 = *reinterpret_cast<const float4*>(wbase + kk * 8 + 4);
                int hb = kk * 32;
                STEPQ(wa4.x, wb4.x, hb + 0)
                STEPQ(wa4.y, wb4.y, hb + 8)
                STEPQ(wa4.z, wb4.z, hb + 16)
                STEPQ(wa4.w, wb4.w, hb + 24)
            }
#undef STEPQ

            float* zb = &sm->z4[ks * 3200 + pid * 4];
            ulonglong2 v;
            v.x = aA0; v.y = aB0; *reinterpret_cast<ulonglong2*>(zb)        = v;
            v.x = aA1; v.y = aB1; *reinterpret_cast<ulonglong2*>(zb + 800)  = v;
            v.x = aA2; v.y = aB2; *reinterpret_cast<ulonglong2*>(zb + 1600) = v;
            v.x = aA3; v.y = aB3; *reinterpret_cast<ulonglong2*>(zb + 2400) = v;
        } else if (tid >= 416 && tid < 448 && t > 0) {
            // logits for step t-1 (hrow holds h(t-1)); warp 13, ~2.25 outputs/thread
            int e = tid - 416;
#pragma unroll
            for (int q = 0; q < 3; q++) {
                int o = e + q * 32;
                if (o < 72) {
                    int lr = o / 9, ld = o - lr * 9;
                    const float4* hr = reinterpret_cast<const float4*>(&sm->hrow[lr * 104]);
                    const float4* wd = reinterpret_cast<const float4*>(&sm->woutT[ld * 104]);
                    float a0 = 0.f, a1 = 0.f, a2 = 0.f, a3 = 0.f;
#pragma unroll
                    for (int kk = 0; kk < 25; kk++) {
                        float4 h4 = hr[kk];
                        float4 w4 = wd[kk];
                        a0 += h4.x * w4.x;
                        a1 += h4.y * w4.y;
                        a2 += h4.z * w4.z;
                        a3 += h4.w * w4.w;
                    }
                    sm->lg[o] = sm->bout[ld] + (a0 + a1) + (a2 + a3);
                }
            }
        }
        __syncthreads();

        // ---- ph2: gates [0..399] || encode s(t+1) [400..415] || softmax(t-1) [416..423]
        //           || raw(t+2) store [448..511]
        if (tid < GG) {
            float2 zc[4];
#pragma unroll
            for (int c = 0; c < 4; c++) {
                int j  = gu + c * HH;
                int bi = (gp * 200 + (j >> 1)) * 4 + ((j & 1) << 1);
                float2 a = *reinterpret_cast<const float2*>(&sm->z4[bi]);
                float2 b = *reinterpret_cast<const float2*>(&sm->z4[3200 + bi]);
                zc[c] = make_float2(a.x + b.x, a.y + b.y);
            }
            float gi0 = sigmoidf_(zc[0].x), gf0 = sigmoidf_(zc[1].x);
            float gg0 = tanhf_(zc[2].x),    go0 = sigmoidf_(zc[3].x);
            c0 = gf0 * c0 + gi0 * gg0;
            float h0 = go0 * tanhf_(c0);

            float gi1 = sigmoidf_(zc[0].y), gf1 = sigmoidf_(zc[1].y);
            float gg1 = tanhf_(zc[2].y),    go1 = sigmoidf_(zc[3].y);
            c1 = gf1 * c1 + gi1 * gg1;
            float h1 = go1 * tanhf_(c1);

            *reinterpret_cast<float2*>(&sm->hT[kh * 8 + 2 * gp]) = make_float2(h0, h1);
            sm->hrow[(2 * gp) * 104 + gu]     = h0;
            sm->hrow[(2 * gp + 1) * 104 + gu] = h1;
        } else if (tid < 416) {
            if ((t + 1) < T_TOT) {
                int e = tid - 400;
                const float* rb = sm->rawS[(t + 1) & 1];
                const float* We = ((t + 1) < T_INP) ? sm->win : sm->wtask;
                const float* be = ((t + 1) < T_INP) ? sm->bin : sm->btask;
#pragma unroll
                for (int q = 0; q < 5; q++) {
                    int o = e + q * 16;
                    if (o < 72) {
                        int sr = o / 9, sf = o - sr * 9;
                        float a = be[sf];
#pragma unroll
                        for (int f = 0; f < 9; f++) a += rb[sr * 9 + f] * We[f * 9 + sf];
                        sm->sT[sf * 8 + sr] = fmaxf(a, 0.0f);
                    }
                }
            }
        } else if (tid < 424 && t > 0) {
            int r = tid - 416;
            float l[9];
            float m = -1e30f;
#pragma unroll
            for (int d = 0; d < 9; d++) { l[d] = sm->lg[r * 9 + d]; m = fmaxf(m, l[d]); }
            float ssum = 0.0f;
#pragma unroll
            for (int d = 0; d < 9; d++) { l[d] = __expf(l[d] - m); ssum += l[d]; }
            float inv = __fdividef(1.0f, ssum);
            float* op = out + ((size_t)(row0 + r) * T_TOT + (t - 1)) * 9;
#pragma unroll
            for (int d = 0; d < 9; d++) op[d] = l[d] * inv;
        }
        if (tid >= 448 && (t + 2) < T_TOT) {
            int j = tid - 448;
            float* rb = sm->rawS[t & 1];
            rb[j] = pv0;
            if (j < 8) rb[j + 64] = pv1;
        }
        __syncthreads();
    }

    // ---------------- epilogue: logits + softmax for t = 575 ----------------
    if (tid < 72) {
        int lr = tid / 9, ld = tid - lr * 9;
        const float4* hr = reinterpret_cast<const float4*>(&sm->hrow[lr * 104]);
        const float4* wd = reinterpret_cast<const float4*>(&sm->woutT[ld * 104]);
        float a0 = 0.f, a1 = 0.f, a2 = 0.f, a3 = 0.f;
#pragma unroll
        for (int kk = 0; kk < 25; kk++) {
            float4 h4 = hr[kk];
            float4 w4 = wd[kk];
            a0 += h4.x * w4.x;
            a1 += h4.y * w4.y;
            a2 += h4.z * w4.z;
            a3 += h4.w * w4.w;
        }
        sm->lg[tid] = sm->bout[ld] + (a0 + a1) + (a2 + a3);
    }
    __syncthreads();
    if (tid < BS) {
        float l[9];
        float m = -1e30f;
#pragma unroll
        for (int d = 0; d < 9; d++) { l[d] = sm->lg[tid * 9 + d]; m = fmaxf(m, l[d]); }
        float ssum = 0.0f;
#pragma unroll
        for (int d = 0; d < 9; d++) { l[d] = __expf(l[d] - m); ssum += l[d]; }
        float inv = __fdividef(1.0f, ssum);
        float* op = out + ((size_t)(row0 + tid) * T_TOT + (T_TOT - 1)) * 9;
#pragma unroll
        for (int d = 0; d < 9; d++) op[d] = l[d] * inv;
    }
}

extern "C" void kernel_launch(void* const* d_in, const int* in_sizes, int n_in,
                              void* d_out, int out_size) {
    const float* input  = (const float*)d_in[0];
    const float* task   = (const float*)d_in[1];
    const float* W_in   = (const float*)d_in[2];
    const float* b_in   = (const float*)d_in[3];
    const float* W_task = (const float*)d_in[4];
    const float* b_task = (const float*)d_in[5];
    const float* W_x    = (const float*)d_in[6];
    const float* W_h    = (const float*)d_in[7];
    const float* b_lstm = (const float*)d_in[8];
    const float* W_out  = (const float*)d_in[9];
    const float* b_out  = (const float*)d_in[10];
    float* out = (float*)d_out;

    cudaFuncSetAttribute(lstm_fused_kernel,
                         cudaFuncAttributeMaxDynamicSharedMemorySize,
                         (int)sizeof(Smem));
    lstm_fused_kernel<<<NBLOCKS, NTHREADS, sizeof(Smem)>>>(
        input, task, W_in, b_in, W_task, b_task,
        W_x, W_h, b_lstm, W_out, b_out, out);
}

// round 12
// speedup vs baseline: 2.1324x; 1.0003x over previous
#include <cuda_runtime.h>
#include <math.h>

// Problem constants
#define BB      1024
#define T_TOT   576
#define T_INP   512
#define T_TASK  64
#define HH      100
#define GG      400
#define DF      9
#define BS      8        // batch rows per block
#define NTHREADS 512
#define NBLOCKS  128     // 128 * 8 = 1024 exactly

#define WQSTR   404      // whQ floats per unit u: 100k*4cols + 4 pad (20u mod 32 bank spiral)
#define HRSTR   108      // hrow/woutT row stride (pad 100->108, 16B mult, conflict-free)

typedef unsigned long long ull;

struct __align__(16) Smem {
    float whQ[HH * WQSTR];     // quad-interleaved W_h: whQ[u*404 + k*4 + c] = W_h[k][u+c*100]  161600 B
    float wxQ[HH * 36];        // wxQ[u*36 + f*4 + c] = W_x[f][u+c*100]                          14400 B
    float blQ[HH * 4];         // bias quad per unit                                              1600 B
    float woutT[DF * HRSTR];   // W_out^T d-major, k padded to 108 with zeros                     3888 B
    float hT[2][HH * 8];       // h, k-major x 8 rows, parity double-buffered                     6400 B
    float hrow[2][BS * HRSTR]; // h row-major (logits), double-buffered, pad zeroed               6912 B
    float sT[2][72];           // encoded features, f-major x 8 rows, double-buffered              576 B
    float rawS[2][72];         // raw features, double-buffered (distance-2 prefetch)              576 B
    float lg[2][72];           // logits, double-buffered                                          576 B
    float win[81], wtask[81], bin[DF], btask[DF], bout[DF];
};
// ~197.3 KB dynamic smem -> 1 block/SM

__device__ __forceinline__ float sigmoidf_(float x) {
    return __fdividef(1.0f, 1.0f + __expf(-x));
}
__device__ __forceinline__ float tanhf_(float x) {
    return 1.0f - __fdividef(2.0f, 1.0f + __expf(2.0f * x));
}
__device__ __forceinline__ void fma2(ull& acc, ull ab, ull cd) {
    asm("fma.rn.f32x2 %0, %1, %2, %0;" : "+l"(acc) : "l"(ab), "l"(cd));
}
__device__ __forceinline__ ull dup2(float w) {
    ull r;
    asm("mov.b64 %0, {%1, %1};" : "=l"(r) : "f"(w));
    return r;
}
__device__ __forceinline__ float2 unpack2(ull v) {
    float2 r;
    asm("mov.b64 {%0, %1}, %2;" : "=f"(r.x), "=f"(r.y) : "l"(v));
    return r;
}

__global__ void __launch_bounds__(NTHREADS, 1)
lstm_fused_kernel(const float* __restrict__ input,  // [1024,512,9]
                  const float* __restrict__ task,   // [1024,64,9]
                  const float* __restrict__ W_in,   // [9,9]
                  const float* __restrict__ b_in,   // [9]
                  const float* __restrict__ W_task, // [9,9]
                  const float* __restrict__ b_task, // [9]
                  const float* __restrict__ W_x,    // [9,400]
                  const float* __restrict__ W_h,    // [100,400]
                  const float* __restrict__ b_lstm, // [400]
                  const float* __restrict__ W_out,  // [100,9]
                  const float* __restrict__ b_out,  // [9]
                  float* __restrict__ out)          // [1024,576,9]
{
    extern __shared__ unsigned char smem_raw[];
    Smem* sm = reinterpret_cast<Smem*>(smem_raw);

    const int tid  = threadIdx.x;
    const int row0 = blockIdx.x * BS;

    // ---------------- prologue: stage weights ----------------
    for (int idx = tid; idx < HH * WQSTR; idx += NTHREADS) {
        int u   = idx / WQSTR;
        int rem = idx - u * WQSTR;
        float v = 0.0f;
        if (rem < 400) {
            int k = rem >> 2, c = rem & 3;
            v = W_h[k * GG + u + c * HH];
        }
        sm->whQ[idx] = v;
    }
    for (int idx = tid; idx < HH * 36; idx += NTHREADS) {
        int u = idx / 36, rem = idx - u * 36;
        int f = rem >> 2, c = rem & 3;
        sm->wxQ[idx] = W_x[f * GG + u + c * HH];
    }
    for (int idx = tid; idx < HH * 4; idx += NTHREADS) {
        int u = idx >> 2, c = idx & 3;
        sm->blQ[idx] = b_lstm[u + c * HH];
    }
    for (int idx = tid; idx < DF * HRSTR; idx += NTHREADS) {
        int d = idx / HRSTR, k = idx - d * HRSTR;
        sm->woutT[idx] = (k < HH) ? W_out[k * DF + d] : 0.0f;
    }
    if (tid < 81) { sm->win[tid] = W_in[tid]; sm->wtask[tid] = W_task[tid]; }
    if (tid < DF) { sm->bin[tid] = b_in[tid]; sm->btask[tid] = b_task[tid]; sm->bout[tid] = b_out[tid]; }
    for (int idx = tid; idx < HH * 8; idx += NTHREADS) { sm->hT[0][idx] = 0.0f; sm->hT[1][idx] = 0.0f; }
    for (int idx = tid; idx < BS * HRSTR; idx += NTHREADS) { sm->hrow[0][idx] = 0.0f; sm->hrow[1][idx] = 0.0f; }

    // GEMM-thread persistent registers
    float bq0 = 0.f, bq1 = 0.f, bq2 = 0.f, bq3 = 0.f;
    if (tid < HH) {
        bq0 = b_lstm[tid];
        bq1 = b_lstm[tid + HH];
        bq2 = b_lstm[tid + 2 * HH];
        bq3 = b_lstm[tid + 3 * HH];
    }
    float cst[8];
#pragma unroll
    for (int j = 0; j < 8; j++) cst[j] = 0.0f;

    __syncthreads();

    // prime: raw(0)->rawS[0], raw(1)->rawS[1], then s(0)->sT[0]
    if (tid < 72) {
        sm->rawS[0][tid] = input[(size_t)(row0 + tid / 9) * (T_INP * 9) + (tid % 9)];
    } else if (tid < 144) {
        int j = tid - 72;
        sm->rawS[1][j] = input[((size_t)(row0 + j / 9) * T_INP + 1) * 9 + (j % 9)];
    }
    __syncthreads();
    if (tid < 72) {
        int sr = tid / 9, sf = tid - sr * 9;
        float a = sm->bin[sf];
#pragma unroll
        for (int f = 0; f < 9; f++) a += sm->rawS[0][sr * 9 + f] * sm->win[f * 9 + sf];
        sm->sT[0][sf * 8 + sr] = fmaxf(a, 0.0f);
    }
    __syncthreads();

    // ---------------- the 576-step scan (ONE barrier per step) ----------------
    for (int t = 0; t < T_TOT; t++) {
        const int rb = t & 1;      // read-buffer parity
        const int wb = 1 - rb;     // write-buffer parity

        // ---- prefetch raw(t+2): issue LDG early (tid 416..487)
        float pv = 0.0f;
        const int pj = tid - 416;
        if (pj >= 0 && pj < 72 && (t + 2) < T_TOT) {
            int tn = t + 2;
            int pr = pj / 9, pc = pj - pr * 9;
            pv = (tn < T_INP)
                     ? input[((size_t)(row0 + pr) * T_INP + tn) * 9 + pc]
                     : task[((size_t)(row0 + pr) * T_TASK + (tn - T_INP)) * 9 + pc];
        }

        if (tid < HH) {
            // ---- fused GEMM + gates: this thread owns unit u = tid
            const int u = tid;
            const float* sb = sm->sT[rb];
            const float* hb = sm->hT[rb];

            ull a00, a01, a02, a03;   // col 0 (i-gate), row pairs (01)(23)(45)(67)
            ull a10, a11, a12, a13;   // col 1 (f)
            ull a20, a21, a22, a23;   // col 2 (g)
            ull a30, a31, a32, a33;   // col 3 (o)
            {
                ull b0 = dup2(bq0), b1 = dup2(bq1), b2 = dup2(bq2), b3 = dup2(bq3);
                a00 = b0; a01 = b0; a02 = b0; a03 = b0;
                a10 = b1; a11 = b1; a12 = b1; a13 = b1;
                a20 = b2; a21 = b2; a22 = b2; a23 = b2;
                a30 = b3; a31 = b3; a32 = b3; a33 = b3;
            }

#define QFMA(W4, VA, VB)                                                         \
            {                                                                    \
                ull dx = dup2((W4).x), dy = dup2((W4).y);                        \
                ull dz = dup2((W4).z), dw = dup2((W4).w);                        \
                fma2(a00, dx, (VA).x); fma2(a01, dx, (VA).y);                    \
                fma2(a02, dx, (VB).x); fma2(a03, dx, (VB).y);                    \
                fma2(a10, dy, (VA).x); fma2(a11, dy, (VA).y);                    \
                fma2(a12, dy, (VB).x); fma2(a13, dy, (VB).y);                    \
                fma2(a20, dz, (VA).x); fma2(a21, dz, (VA).y);                    \
                fma2(a22, dz, (VB).x); fma2(a23, dz, (VB).y);                    \
                fma2(a30, dw, (VA).x); fma2(a31, dw, (VA).y);                    \
                fma2(a32, dw, (VB).x); fma2(a33, dw, (VB).y);                    \
            }

            // s @ W_x part (9 features)
            const float* xq = &sm->wxQ[u * 36];
#pragma unroll
            for (int f = 0; f < 9; f++) {
                float4 x4 = *reinterpret_cast<const float4*>(&xq[f * 4]);
                ulonglong2 sA = *reinterpret_cast<const ulonglong2*>(&sb[f * 8]);
                ulonglong2 sB = *reinterpret_cast<const ulonglong2*>(&sb[f * 8 + 4]);
                QFMA(x4, sA, sB)
            }

            // h @ W_h part (k = 0..99)
            const float* wq = &sm->whQ[u * WQSTR];
#pragma unroll 4
            for (int k = 0; k < HH; k++) {
                float4 w4 = *reinterpret_cast<const float4*>(&wq[k * 4]);
                ulonglong2 hA = *reinterpret_cast<const ulonglong2*>(&hb[k * 8]);
                ulonglong2 hB = *reinterpret_cast<const ulonglong2*>(&hb[k * 8 + 4]);
                QFMA(w4, hA, hB)
            }
#undef QFMA

            // gates: all z in registers — no smem round-trip, no extra barrier
            float zi[8], zf[8], zg[8], zo[8];
            { float2 p; p = unpack2(a00); zi[0]=p.x; zi[1]=p.y; p = unpack2(a01); zi[2]=p.x; zi[3]=p.y;
              p = unpack2(a02); zi[4]=p.x; zi[5]=p.y; p = unpack2(a03); zi[6]=p.x; zi[7]=p.y; }
            { float2 p; p = unpack2(a10); zf[0]=p.x; zf[1]=p.y; p = unpack2(a11); zf[2]=p.x; zf[3]=p.y;
              p = unpack2(a12); zf[4]=p.x; zf[5]=p.y; p = unpack2(a13); zf[6]=p.x; zf[7]=p.y; }
            { float2 p; p = unpack2(a20); zg[0]=p.x; zg[1]=p.y; p = unpack2(a21); zg[2]=p.x; zg[3]=p.y;
              p = unpack2(a22); zg[4]=p.x; zg[5]=p.y; p = unpack2(a23); zg[6]=p.x; zg[7]=p.y; }
            { float2 p; p = unpack2(a30); zo[0]=p.x; zo[1]=p.y; p = unpack2(a31); zo[2]=p.x; zo[3]=p.y;
              p = unpack2(a32); zo[4]=p.x; zo[5]=p.y; p = unpack2(a33); zo[6]=p.x; zo[7]=p.y; }

            float hv[8];
#pragma unroll
            for (int j = 0; j < 8; j++) {
                float gi = sigmoidf_(zi[j]);
                float gf = sigmoidf_(zf[j]);
                float gg = tanhf_(zg[j]);
                float go = sigmoidf_(zo[j]);
                cst[j] = gf * cst[j] + gi * gg;
                hv[j]  = go * tanhf_(cst[j]);
            }

            float* hw = sm->hT[wb];
            *reinterpret_cast<float4*>(&hw[u * 8])     = make_float4(hv[0], hv[1], hv[2], hv[3]);
            *reinterpret_cast<float4*>(&hw[u * 8 + 4]) = make_float4(hv[4], hv[5], hv[6], hv[7]);
            float* hr = sm->hrow[wb];
#pragma unroll
            for (int j = 0; j < 8; j++) hr[j * HRSTR + u] = hv[j];
        } else if (tid >= 192 && tid < 264) {
            // ---- logits(t-1) from hrow[rb] = h(t-1)
            if (t > 0) {
                int e  = tid - 192;
                int lr = e / 9, ld = e - lr * 9;
                const float4* hr4 = reinterpret_cast<const float4*>(&sm->hrow[rb][lr * HRSTR]);
                const float4* wd4 = reinterpret_cast<const float4*>(&sm->woutT[ld * HRSTR]);
                float s0 = 0.f, s1 = 0.f, s2 = 0.f, s3 = 0.f;
#pragma unroll
                for (int kk = 0; kk < 27; kk++) {
                    float4 h4 = hr4[kk];
                    float4 w4 = wd4[kk];
                    s0 += h4.x * w4.x;
                    s1 += h4.y * w4.y;
                    s2 += h4.z * w4.z;
                    s3 += h4.w * w4.w;
                }
                sm->lg[wb][e] = sm->bout[ld] + (s0 + s1) + (s2 + s3);
            }
        } else if (tid >= 288 && tid < 360) {
            // ---- encode s(t+1) into sT[wb] from rawS[wb]
            if ((t + 1) < T_TOT) {
                int e  = tid - 288;
                int sr = e / 9, sf = e - sr * 9;
                const float* rbuf = sm->rawS[wb];
                const float* We = ((t + 1) < T_INP) ? sm->win : sm->wtask;
                const float* be = ((t + 1) < T_INP) ? sm->bin : sm->btask;
                float a = be[sf];
#pragma unroll
                for (int f = 0; f < 9; f++) a += rbuf[sr * 9 + f] * We[f * 9 + sf];
                sm->sT[wb][sf * 8 + sr] = fmaxf(a, 0.0f);
            }
        } else if (tid >= 376 && tid < 384) {
            // ---- softmax + store for step t-2 from lg[rb]
            if (t >= 2) {
                int r = tid - 376;
                float l[9];
                float m = -1e30f;
#pragma unroll
                for (int d = 0; d < 9; d++) { l[d] = sm->lg[rb][r * 9 + d]; m = fmaxf(m, l[d]); }
                float ssum = 0.0f;
#pragma unroll
                for (int d = 0; d < 9; d++) { l[d] = __expf(l[d] - m); ssum += l[d]; }
                float inv = __fdividef(1.0f, ssum);
                float* op = out + ((size_t)(row0 + r) * T_TOT + (t - 2)) * 9;
#pragma unroll
                for (int d = 0; d < 9; d++) op[d] = l[d] * inv;
            }
        }

        // ---- land prefetched raw(t+2) into rawS[rb] (= parity of t+2)
        if (pj >= 0 && pj < 72 && (t + 2) < T_TOT) sm->rawS[rb][pj] = pv;

        __syncthreads();
    }

    // ---------------- epilogue: logits(575), softmax(574), softmax(575) ----------------
    // h(575) is in buffers[0]; lg[0] holds logits(574).
    if (tid < 72) {
        int lr = tid / 9, ld = tid - lr * 9;
        const float4* hr4 = reinterpret_cast<const float4*>(&sm->hrow[0][lr * HRSTR]);
        const float4* wd4 = reinterpret_cast<const float4*>(&sm->woutT[ld * HRSTR]);
        float s0 = 0.f, s1 = 0.f, s2 = 0.f, s3 = 0.f;
#pragma unroll
        for (int kk = 0; kk < 27; kk++) {
            float4 h4 = hr4[kk];
            float4 w4 = wd4[kk];
            s0 += h4.x * w4.x;
            s1 += h4.y * w4.y;
            s2 += h4.z * w4.z;
            s3 += h4.w * w4.w;
        }
        sm->lg[1][tid] = sm->bout[ld] + (s0 + s1) + (s2 + s3);
    } else if (tid >= 128 && tid < 136) {
        int r = tid - 128;
        float l[9];
        float m = -1e30f;
#pragma unroll
        for (int d = 0; d < 9; d++) { l[d] = sm->lg[0][r * 9 + d]; m = fmaxf(m, l[d]); }
        float ssum = 0.0f;
#pragma unroll
        for (int d = 0; d < 9; d++) { l[d] = __expf(l[d] - m); ssum += l[d]; }
        float inv = __fdividef(1.0f, ssum);
        float* op = out + ((size_t)(row0 + r) * T_TOT + (T_TOT - 2)) * 9;
#pragma unroll
        for (int d = 0; d < 9; d++) op[d] = l[d] * inv;
    }
    __syncthreads();
    if (tid < BS) {
        float l[9];
        float m = -1e30f;
#pragma unroll
        for (int d = 0; d < 9; d++) { l[d] = sm->lg[1][tid * 9 + d]; m = fmaxf(m, l[d]); }
        float ssum = 0.0f;
#pragma unroll
        for (int d = 0; d < 9; d++) { l[d] = __expf(l[d] - m); ssum += l[d]; }
        float inv = __fdividef(1.0f, ssum);
        float* op = out + ((size_t)(row0 + tid) * T_TOT + (T_TOT - 1)) * 9;
#pragma unroll
        for (int d = 0; d < 9; d++) op[d] = l[d] * inv;
    }
}

extern "C" void kernel_launch(void* const* d_in, const int* in_sizes, int n_in,
                              void* d_out, int out_size) {
    const float* input  = (const float*)d_in[0];
    const float* task   = (const float*)d_in[1];
    const float* W_in   = (const float*)d_in[2];
    const float* b_in   = (const float*)d_in[3];
    const float* W_task = (const float*)d_in[4];
    const float* b_task = (const float*)d_in[5];
    const float* W_x    = (const float*)d_in[6];
    const float* W_h    = (const float*)d_in[7];
    const float* b_lstm = (const float*)d_in[8];
    const float* W_out  = (const float*)d_in[9];
    const float* b_out  = (const float*)d_in[10];
    float* out = (float*)d_out;

    cudaFuncSetAttribute(lstm_fused_kernel,
                         cudaFuncAttributeMaxDynamicSharedMemorySize,
                         (int)sizeof(Smem));
    lstm_fused_kernel<<<NBLOCKS, NTHREADS, sizeof(Smem)>>>(
        input, task, W_in, b_in, W_task, b_task,
        W_x, W_h, b_lstm, W_out, b_out, out);
}